// round 1
// baseline (speedup 1.0000x reference)
#include <cuda_runtime.h>

// PGCNCritic fused kernel, fp32 SIMT baseline.
// One CTA per batch element (grid = 16384, 256 threads).
//
// Phases (per CTA):
//  1. Stage obs + embedding weights to SMEM; build adjacency bitmasks + d^-1/2 via ballot.
//  2. Embedding -> x (64 nodes x 64 hidden) in SMEM.
//  3. 3x GCN layer: scale rows by dinv, sparse-aggregate via bitmask (warp-uniform),
//     scale by dinv_i, then 64x64x64 register-tiled matmul with W in SMEM, ReLU.
//  4. Head: mean over device nodes; u[128] = bf1 + Wf1_mean^T mean + Wf1_srv^T h63
//     (constant over nodes -> 3x FLOP reduction); z_i = Wf1_dev^T h_i + u;
//     out_i = relu(z_i) . Wf2 + bf2, reduced via shfl.

#define FULLMASK 0xffffffffu

__global__ __launch_bounds__(256, 4)
void pgcn_kernel(
    const float* __restrict__ dev_obs,   // (B,63,14)
    const float* __restrict__ srv_obs,   // (B,3)
    const float* __restrict__ adj,       // (B,64,64)
    const float* __restrict__ W_dev,     // (14,64)
    const float* __restrict__ b_dev,     // (64)
    const float* __restrict__ W_srv,     // (3,64)
    const float* __restrict__ b_srv,     // (64)
    const float* __restrict__ W1, const float* __restrict__ b1,
    const float* __restrict__ W2, const float* __restrict__ b2,
    const float* __restrict__ W3, const float* __restrict__ b3,
    const float* __restrict__ Wf1,       // (192,128)
    const float* __restrict__ bf1,       // (128)
    const float* __restrict__ Wf2,       // (128)
    const float* __restrict__ bf2,       // (1)
    float* __restrict__ out)             // (B,63)
{
    __shared__ __align__(16) float s_a[4096];      // node features (64x64)
    __shared__ __align__(16) float s_pool[8192];   // layers: [t(4096) | W(4096)]; head: Wf1_dev(64x128)
    __shared__ float s_obs[896];                   // 882 device obs + 3 server obs
    __shared__ unsigned s_mlo[64], s_mhi[64];      // adjacency row bitmasks
    __shared__ float s_dinv[64];
    __shared__ float s_mean[64];
    __shared__ float s_u[128];
    __shared__ float s_wf2[128];

    const int b    = blockIdx.x;
    const int tid  = threadIdx.x;
    const int lane = tid & 31;
    const int warp = tid >> 5;

    // ---------------- Phase 1: stage inputs, build adjacency masks ----------------
    for (int i = tid; i < 882; i += 256) s_obs[i] = dev_obs[b * 882 + i];
    if (tid < 3) s_obs[882 + tid] = srv_obs[b * 3 + tid];
    // embedding weights into s_pool: W_dev (896 floats) then W_srv (192 floats)
    for (int i = tid; i < 896; i += 256) s_pool[i] = W_dev[i];
    if (tid < 192) s_pool[896 + tid] = W_srv[tid];

    // adjacency: each warp does 8 rows; values are exactly 0.0 or 1.0
    {
        const float* arow = adj + (size_t)b * 4096;
        for (int r = warp; r < 64; r += 8) {
            float v0 = arow[r * 64 + lane];
            float v1 = arow[r * 64 + 32 + lane];
            unsigned m0 = __ballot_sync(FULLMASK, v0 != 0.0f);
            unsigned m1 = __ballot_sync(FULLMASK, v1 != 0.0f);
            if (lane == 0) {
                s_mlo[r] = m0;
                s_mhi[r] = m1;
                float deg = (float)(__popc(m0) + __popc(m1));
                s_dinv[r] = rsqrtf(fmaxf(deg, 1.0f));
            }
        }
    }
    __syncthreads();

    // ---------------- Phase 2: embedding -> s_a ----------------
    for (int idx = tid; idx < 4096; idx += 256) {
        int n = idx >> 6, c = idx & 63;
        float acc;
        if (n < 63) {
            acc = b_dev[c];
            const float* o = s_obs + n * 14;
            #pragma unroll
            for (int k = 0; k < 14; k++) acc = fmaf(o[k], s_pool[k * 64 + c], acc);
        } else {
            acc = b_srv[c];
            #pragma unroll
            for (int k = 0; k < 3; k++) acc = fmaf(s_obs[882 + k], s_pool[896 + k * 64 + c], acc);
        }
        s_a[idx] = fmaxf(acc, 0.0f);
    }
    __syncthreads();

    // ---------------- Phase 3: 3 GCN layers ----------------
    float* s_t = s_pool;          // aggregation result (4096)
    float* s_w = s_pool + 4096;   // layer weight (4096)

    const float* Ws[3] = {W1, W2, W3};
    const float* bs[3] = {b1, b2, b3};

    #pragma unroll 1
    for (int L = 0; L < 3; L++) {
        // stage W, scale input rows by dinv[j]
        for (int i = tid; i < 4096; i += 256) s_w[i] = Ws[L][i];
        for (int idx = tid; idx < 4096; idx += 256) s_a[idx] *= s_dinv[idx >> 6];
        __syncthreads();

        // sparse aggregation: t[r][c] = dinv[r] * sum_{j in mask_r} (dinv[j]*x[j][c])
        for (int r = warp; r < 64; r += 8) {
            unsigned m0 = s_mlo[r], m1 = s_mhi[r];
            float a0 = 0.0f, a1 = 0.0f;
            while (m0) {
                int j = __ffs(m0) - 1; m0 &= m0 - 1;
                a0 += s_a[j * 64 + lane];
                a1 += s_a[j * 64 + 32 + lane];
            }
            while (m1) {
                int j = __ffs(m1) + 31; m1 &= m1 - 1;
                a0 += s_a[j * 64 + lane];
                a1 += s_a[j * 64 + 32 + lane];
            }
            float di = s_dinv[r];
            s_t[r * 64 + lane]      = di * a0;
            s_t[r * 64 + 32 + lane] = di * a1;
        }
        __syncthreads();

        // h = relu(t @ W + b): thread computes 2 rows x 8 cols
        {
            const int rp = tid >> 3;        // 0..31
            const int cg = tid & 7;         // 0..7
            const int r0 = rp * 2, r1 = r0 + 1;
            const int c0 = cg * 8;
            float acc0[8] = {0,0,0,0,0,0,0,0};
            float acc1[8] = {0,0,0,0,0,0,0,0};
            #pragma unroll 8
            for (int k = 0; k < 64; k++) {
                float t0 = s_t[r0 * 64 + k];
                float t1 = s_t[r1 * 64 + k];
                float4 wA = *(const float4*)(s_w + k * 64 + c0);
                float4 wB = *(const float4*)(s_w + k * 64 + c0 + 4);
                acc0[0] = fmaf(t0, wA.x, acc0[0]); acc0[1] = fmaf(t0, wA.y, acc0[1]);
                acc0[2] = fmaf(t0, wA.z, acc0[2]); acc0[3] = fmaf(t0, wA.w, acc0[3]);
                acc0[4] = fmaf(t0, wB.x, acc0[4]); acc0[5] = fmaf(t0, wB.y, acc0[5]);
                acc0[6] = fmaf(t0, wB.z, acc0[6]); acc0[7] = fmaf(t0, wB.w, acc0[7]);
                acc1[0] = fmaf(t1, wA.x, acc1[0]); acc1[1] = fmaf(t1, wA.y, acc1[1]);
                acc1[2] = fmaf(t1, wA.z, acc1[2]); acc1[3] = fmaf(t1, wA.w, acc1[3]);
                acc1[4] = fmaf(t1, wB.x, acc1[4]); acc1[5] = fmaf(t1, wB.y, acc1[5]);
                acc1[6] = fmaf(t1, wB.z, acc1[6]); acc1[7] = fmaf(t1, wB.w, acc1[7]);
            }
            const float* bb = bs[L];
            #pragma unroll
            for (int q = 0; q < 8; q++) {
                float bias = bb[c0 + q];
                s_a[r0 * 64 + c0 + q] = fmaxf(acc0[q] + bias, 0.0f);
                s_a[r1 * 64 + c0 + q] = fmaxf(acc1[q] + bias, 0.0f);
            }
        }
        __syncthreads();
    }

    // ---------------- Phase 4: critic head ----------------
    // mean over device nodes (rows 0..62)
    if (tid < 64) {
        float s = 0.0f;
        for (int i = 0; i < 63; i++) s += s_a[i * 64 + tid];
        s_mean[tid] = s * (1.0f / 63.0f);
    }
    __syncthreads();

    // u[m] = bf1[m] + Wf1_mean^T mean + Wf1_srv^T h63  (constant over nodes)
    // concurrently: threads >=128 stage Wf1_dev (first 64x128 block) + Wf2 into SMEM
    if (tid < 128) {
        float acc = bf1[tid];
        #pragma unroll 4
        for (int k = 0; k < 64; k++) acc = fmaf(s_mean[k],        Wf1[(64  + k) * 128 + tid], acc);
        #pragma unroll 4
        for (int k = 0; k < 64; k++) acc = fmaf(s_a[63 * 64 + k], Wf1[(128 + k) * 128 + tid], acc);
        s_u[tid] = acc;
    } else {
        for (int i = tid - 128; i < 8192; i += 128) s_pool[i] = Wf1[i];
        if (tid - 128 < 128) s_wf2[tid - 128] = Wf2[tid - 128];
    }
    __syncthreads();

    // z_i = h_i @ Wf1_dev + u ; out_i = relu(z_i).Wf2 + bf2
    // thread computes 2 rows x 16 cols of z in registers, then partial dot + shfl reduce
    {
        const int rp = tid >> 3;        // 0..31 -> rows 2rp, 2rp+1
        const int cg = tid & 7;         // 0..7  -> cols 16*cg..+15
        const int r0 = rp * 2, r1 = r0 + 1;
        const int c0 = cg * 16;
        float z0[16], z1[16];
        #pragma unroll
        for (int q = 0; q < 16; q++) { z0[q] = 0.0f; z1[q] = 0.0f; }

        #pragma unroll 4
        for (int k = 0; k < 64; k++) {
            float h0 = s_a[r0 * 64 + k];
            float h1 = s_a[r1 * 64 + k];
            #pragma unroll
            for (int q = 0; q < 4; q++) {
                float4 w = *(const float4*)(s_pool + k * 128 + c0 + q * 4);
                z0[q*4+0] = fmaf(h0, w.x, z0[q*4+0]);
                z0[q*4+1] = fmaf(h0, w.y, z0[q*4+1]);
                z0[q*4+2] = fmaf(h0, w.z, z0[q*4+2]);
                z0[q*4+3] = fmaf(h0, w.w, z0[q*4+3]);
                z1[q*4+0] = fmaf(h1, w.x, z1[q*4+0]);
                z1[q*4+1] = fmaf(h1, w.y, z1[q*4+1]);
                z1[q*4+2] = fmaf(h1, w.z, z1[q*4+2]);
                z1[q*4+3] = fmaf(h1, w.w, z1[q*4+3]);
            }
        }

        float p0 = 0.0f, p1 = 0.0f;
        #pragma unroll
        for (int q = 0; q < 16; q++) {
            float uu = s_u[c0 + q];
            float wf = s_wf2[c0 + q];
            p0 = fmaf(fmaxf(z0[q] + uu, 0.0f), wf, p0);
            p1 = fmaf(fmaxf(z1[q] + uu, 0.0f), wf, p1);
        }
        // reduce over the 8-lane column groups (lanes sharing rp)
        #pragma unroll
        for (int off = 1; off < 8; off <<= 1) {
            p0 += __shfl_xor_sync(FULLMASK, p0, off);
            p1 += __shfl_xor_sync(FULLMASK, p1, off);
        }
        if (cg == 0) {
            float bias = bf2[0];
            if (r0 < 63) out[(size_t)b * 63 + r0] = p0 + bias;
            if (r1 < 63) out[(size_t)b * 63 + r1] = p1 + bias;
        }
    }
}

extern "C" void kernel_launch(void* const* d_in, const int* in_sizes, int n_in,
                              void* d_out, int out_size)
{
    (void)in_sizes; (void)n_in; (void)out_size;
    pgcn_kernel<<<16384, 256>>>(
        (const float*)d_in[0],  // device_obs
        (const float*)d_in[1],  // server_obs
        (const float*)d_in[2],  // adjacency
        (const float*)d_in[3],  // W_dev
        (const float*)d_in[4],  // b_dev
        (const float*)d_in[5],  // W_srv
        (const float*)d_in[6],  // b_srv
        (const float*)d_in[7],  // W1
        (const float*)d_in[8],  // b1
        (const float*)d_in[9],  // W2
        (const float*)d_in[10], // b2
        (const float*)d_in[11], // W3
        (const float*)d_in[12], // b3
        (const float*)d_in[13], // Wf1
        (const float*)d_in[14], // bf1
        (const float*)d_in[15], // Wf2
        (const float*)d_in[16], // bf2
        (float*)d_out);
}

// round 2
// speedup vs baseline: 1.0002x; 1.0002x over previous
#include <cuda_runtime.h>

// PGCNCritic fused kernel, fp32 SIMT baseline.
// One CTA per batch element (grid = 16384, 256 threads).
//
// Phases (per CTA):
//  1. Stage obs + embedding weights to SMEM; build adjacency bitmasks + d^-1/2 via ballot.
//  2. Embedding -> x (64 nodes x 64 hidden) in SMEM.
//  3. 3x GCN layer: scale rows by dinv, sparse-aggregate via bitmask (warp-uniform),
//     scale by dinv_i, then 64x64x64 register-tiled matmul with W in SMEM, ReLU.
//  4. Head: mean over device nodes; u[128] = bf1 + Wf1_mean^T mean + Wf1_srv^T h63
//     (constant over nodes -> 3x FLOP reduction); z_i = Wf1_dev^T h_i + u;
//     out_i = relu(z_i) . Wf2 + bf2, reduced via shfl.

#define FULLMASK 0xffffffffu

__global__ __launch_bounds__(256, 4)
void pgcn_kernel(
    const float* __restrict__ dev_obs,   // (B,63,14)
    const float* __restrict__ srv_obs,   // (B,3)
    const float* __restrict__ adj,       // (B,64,64)
    const float* __restrict__ W_dev,     // (14,64)
    const float* __restrict__ b_dev,     // (64)
    const float* __restrict__ W_srv,     // (3,64)
    const float* __restrict__ b_srv,     // (64)
    const float* __restrict__ W1, const float* __restrict__ b1,
    const float* __restrict__ W2, const float* __restrict__ b2,
    const float* __restrict__ W3, const float* __restrict__ b3,
    const float* __restrict__ Wf1,       // (192,128)
    const float* __restrict__ bf1,       // (128)
    const float* __restrict__ Wf2,       // (128)
    const float* __restrict__ bf2,       // (1)
    float* __restrict__ out)             // (B,63)
{
    __shared__ __align__(16) float s_a[4096];      // node features (64x64)
    __shared__ __align__(16) float s_pool[8192];   // layers: [t(4096) | W(4096)]; head: Wf1_dev(64x128)
    __shared__ float s_obs[896];                   // 882 device obs + 3 server obs
    __shared__ unsigned s_mlo[64], s_mhi[64];      // adjacency row bitmasks
    __shared__ float s_dinv[64];
    __shared__ float s_mean[64];
    __shared__ float s_u[128];
    __shared__ float s_wf2[128];

    const int b    = blockIdx.x;
    const int tid  = threadIdx.x;
    const int lane = tid & 31;
    const int warp = tid >> 5;

    // ---------------- Phase 1: stage inputs, build adjacency masks ----------------
    for (int i = tid; i < 882; i += 256) s_obs[i] = dev_obs[b * 882 + i];
    if (tid < 3) s_obs[882 + tid] = srv_obs[b * 3 + tid];
    // embedding weights into s_pool: W_dev (896 floats) then W_srv (192 floats)
    for (int i = tid; i < 896; i += 256) s_pool[i] = W_dev[i];
    if (tid < 192) s_pool[896 + tid] = W_srv[tid];

    // adjacency: each warp does 8 rows; values are exactly 0.0 or 1.0
    {
        const float* arow = adj + (size_t)b * 4096;
        for (int r = warp; r < 64; r += 8) {
            float v0 = arow[r * 64 + lane];
            float v1 = arow[r * 64 + 32 + lane];
            unsigned m0 = __ballot_sync(FULLMASK, v0 != 0.0f);
            unsigned m1 = __ballot_sync(FULLMASK, v1 != 0.0f);
            if (lane == 0) {
                s_mlo[r] = m0;
                s_mhi[r] = m1;
                float deg = (float)(__popc(m0) + __popc(m1));
                s_dinv[r] = rsqrtf(fmaxf(deg, 1.0f));
            }
        }
    }
    __syncthreads();

    // ---------------- Phase 2: embedding -> s_a ----------------
    for (int idx = tid; idx < 4096; idx += 256) {
        int n = idx >> 6, c = idx & 63;
        float acc;
        if (n < 63) {
            acc = b_dev[c];
            const float* o = s_obs + n * 14;
            #pragma unroll
            for (int k = 0; k < 14; k++) acc = fmaf(o[k], s_pool[k * 64 + c], acc);
        } else {
            acc = b_srv[c];
            #pragma unroll
            for (int k = 0; k < 3; k++) acc = fmaf(s_obs[882 + k], s_pool[896 + k * 64 + c], acc);
        }
        s_a[idx] = fmaxf(acc, 0.0f);
    }
    __syncthreads();

    // ---------------- Phase 3: 3 GCN layers ----------------
    float* s_t = s_pool;          // aggregation result (4096)
    float* s_w = s_pool + 4096;   // layer weight (4096)

    const float* Ws[3] = {W1, W2, W3};
    const float* bs[3] = {b1, b2, b3};

    #pragma unroll 1
    for (int L = 0; L < 3; L++) {
        // stage W, scale input rows by dinv[j]
        for (int i = tid; i < 4096; i += 256) s_w[i] = Ws[L][i];
        for (int idx = tid; idx < 4096; idx += 256) s_a[idx] *= s_dinv[idx >> 6];
        __syncthreads();

        // sparse aggregation: t[r][c] = dinv[r] * sum_{j in mask_r} (dinv[j]*x[j][c])
        for (int r = warp; r < 64; r += 8) {
            unsigned m0 = s_mlo[r], m1 = s_mhi[r];
            float a0 = 0.0f, a1 = 0.0f;
            while (m0) {
                int j = __ffs(m0) - 1; m0 &= m0 - 1;
                a0 += s_a[j * 64 + lane];
                a1 += s_a[j * 64 + 32 + lane];
            }
            while (m1) {
                int j = __ffs(m1) + 31; m1 &= m1 - 1;
                a0 += s_a[j * 64 + lane];
                a1 += s_a[j * 64 + 32 + lane];
            }
            float di = s_dinv[r];
            s_t[r * 64 + lane]      = di * a0;
            s_t[r * 64 + 32 + lane] = di * a1;
        }
        __syncthreads();

        // h = relu(t @ W + b): thread computes 2 rows x 8 cols
        {
            const int rp = tid >> 3;        // 0..31
            const int cg = tid & 7;         // 0..7
            const int r0 = rp * 2, r1 = r0 + 1;
            const int c0 = cg * 8;
            float acc0[8] = {0,0,0,0,0,0,0,0};
            float acc1[8] = {0,0,0,0,0,0,0,0};
            #pragma unroll 8
            for (int k = 0; k < 64; k++) {
                float t0 = s_t[r0 * 64 + k];
                float t1 = s_t[r1 * 64 + k];
                float4 wA = *(const float4*)(s_w + k * 64 + c0);
                float4 wB = *(const float4*)(s_w + k * 64 + c0 + 4);
                acc0[0] = fmaf(t0, wA.x, acc0[0]); acc0[1] = fmaf(t0, wA.y, acc0[1]);
                acc0[2] = fmaf(t0, wA.z, acc0[2]); acc0[3] = fmaf(t0, wA.w, acc0[3]);
                acc0[4] = fmaf(t0, wB.x, acc0[4]); acc0[5] = fmaf(t0, wB.y, acc0[5]);
                acc0[6] = fmaf(t0, wB.z, acc0[6]); acc0[7] = fmaf(t0, wB.w, acc0[7]);
                acc1[0] = fmaf(t1, wA.x, acc1[0]); acc1[1] = fmaf(t1, wA.y, acc1[1]);
                acc1[2] = fmaf(t1, wA.z, acc1[2]); acc1[3] = fmaf(t1, wA.w, acc1[3]);
                acc1[4] = fmaf(t1, wB.x, acc1[4]); acc1[5] = fmaf(t1, wB.y, acc1[5]);
                acc1[6] = fmaf(t1, wB.z, acc1[6]); acc1[7] = fmaf(t1, wB.w, acc1[7]);
            }
            const float* bb = bs[L];
            #pragma unroll
            for (int q = 0; q < 8; q++) {
                float bias = bb[c0 + q];
                s_a[r0 * 64 + c0 + q] = fmaxf(acc0[q] + bias, 0.0f);
                s_a[r1 * 64 + c0 + q] = fmaxf(acc1[q] + bias, 0.0f);
            }
        }
        __syncthreads();
    }

    // ---------------- Phase 4: critic head ----------------
    // mean over device nodes (rows 0..62)
    if (tid < 64) {
        float s = 0.0f;
        for (int i = 0; i < 63; i++) s += s_a[i * 64 + tid];
        s_mean[tid] = s * (1.0f / 63.0f);
    }
    __syncthreads();

    // u[m] = bf1[m] + Wf1_mean^T mean + Wf1_srv^T h63  (constant over nodes)
    // concurrently: threads >=128 stage Wf1_dev (first 64x128 block) + Wf2 into SMEM
    if (tid < 128) {
        float acc = bf1[tid];
        #pragma unroll 4
        for (int k = 0; k < 64; k++) acc = fmaf(s_mean[k],        Wf1[(64  + k) * 128 + tid], acc);
        #pragma unroll 4
        for (int k = 0; k < 64; k++) acc = fmaf(s_a[63 * 64 + k], Wf1[(128 + k) * 128 + tid], acc);
        s_u[tid] = acc;
    } else {
        for (int i = tid - 128; i < 8192; i += 128) s_pool[i] = Wf1[i];
        if (tid - 128 < 128) s_wf2[tid - 128] = Wf2[tid - 128];
    }
    __syncthreads();

    // z_i = h_i @ Wf1_dev + u ; out_i = relu(z_i).Wf2 + bf2
    // thread computes 2 rows x 16 cols of z in registers, then partial dot + shfl reduce
    {
        const int rp = tid >> 3;        // 0..31 -> rows 2rp, 2rp+1
        const int cg = tid & 7;         // 0..7  -> cols 16*cg..+15
        const int r0 = rp * 2, r1 = r0 + 1;
        const int c0 = cg * 16;
        float z0[16], z1[16];
        #pragma unroll
        for (int q = 0; q < 16; q++) { z0[q] = 0.0f; z1[q] = 0.0f; }

        #pragma unroll 4
        for (int k = 0; k < 64; k++) {
            float h0 = s_a[r0 * 64 + k];
            float h1 = s_a[r1 * 64 + k];
            #pragma unroll
            for (int q = 0; q < 4; q++) {
                float4 w = *(const float4*)(s_pool + k * 128 + c0 + q * 4);
                z0[q*4+0] = fmaf(h0, w.x, z0[q*4+0]);
                z0[q*4+1] = fmaf(h0, w.y, z0[q*4+1]);
                z0[q*4+2] = fmaf(h0, w.z, z0[q*4+2]);
                z0[q*4+3] = fmaf(h0, w.w, z0[q*4+3]);
                z1[q*4+0] = fmaf(h1, w.x, z1[q*4+0]);
                z1[q*4+1] = fmaf(h1, w.y, z1[q*4+1]);
                z1[q*4+2] = fmaf(h1, w.z, z1[q*4+2]);
                z1[q*4+3] = fmaf(h1, w.w, z1[q*4+3]);
            }
        }

        float p0 = 0.0f, p1 = 0.0f;
        #pragma unroll
        for (int q = 0; q < 16; q++) {
            float uu = s_u[c0 + q];
            float wf = s_wf2[c0 + q];
            p0 = fmaf(fmaxf(z0[q] + uu, 0.0f), wf, p0);
            p1 = fmaf(fmaxf(z1[q] + uu, 0.0f), wf, p1);
        }
        // reduce over the 8-lane column groups (lanes sharing rp)
        #pragma unroll
        for (int off = 1; off < 8; off <<= 1) {
            p0 += __shfl_xor_sync(FULLMASK, p0, off);
            p1 += __shfl_xor_sync(FULLMASK, p1, off);
        }
        if (cg == 0) {
            float bias = bf2[0];
            if (r0 < 63) out[(size_t)b * 63 + r0] = p0 + bias;
            if (r1 < 63) out[(size_t)b * 63 + r1] = p1 + bias;
        }
    }
}

extern "C" void kernel_launch(void* const* d_in, const int* in_sizes, int n_in,
                              void* d_out, int out_size)
{
    (void)in_sizes; (void)n_in; (void)out_size;
    pgcn_kernel<<<16384, 256>>>(
        (const float*)d_in[0],  // device_obs
        (const float*)d_in[1],  // server_obs
        (const float*)d_in[2],  // adjacency
        (const float*)d_in[3],  // W_dev
        (const float*)d_in[4],  // b_dev
        (const float*)d_in[5],  // W_srv
        (const float*)d_in[6],  // b_srv
        (const float*)d_in[7],  // W1
        (const float*)d_in[8],  // b1
        (const float*)d_in[9],  // W2
        (const float*)d_in[10], // b2
        (const float*)d_in[11], // W3
        (const float*)d_in[12], // b3
        (const float*)d_in[13], // Wf1
        (const float*)d_in[14], // bf1
        (const float*)d_in[15], // Wf2
        (const float*)d_in[16], // bf2
        (float*)d_out);
}